// round 1
// baseline (speedup 1.0000x reference)
#include <cuda_runtime.h>
#include <cuda_bf16.h>

#define NN 100000
#define EE 3200000
#define F_IN 512
#define H1 4
#define C1 8
#define D1 32   // H1*C1
#define D2 8    // num classes

// -------- scratch (device globals; no allocation allowed) --------
__device__ float g_xp1[NN * D1];     // layer-1 transformed features [N,4,8]
__device__ float g_as1[NN * H1];
__device__ float g_ad1[NN * H1];
__device__ float g_den1[NN * H1];
__device__ float g_h[NN * D1];       // layer-1 aggregate (pre-elu accum)
__device__ float g_xp2[NN * D2];
__device__ float g_as2[NN];
__device__ float g_ad2[NN];
__device__ float g_den2[NN];

__device__ __forceinline__ void red_add_v4(float* p, float a, float b, float c, float d) {
    asm volatile("red.global.add.v4.f32 [%0], {%1,%2,%3,%4};"
                 :: "l"(p), "f"(a), "f"(b), "f"(c), "f"(d) : "memory");
}

__device__ __forceinline__ float lrelu(float v) { return v > 0.f ? v : 0.2f * v; }

// -------- zero scratch + out --------
__global__ void zero_kernel(float* __restrict__ out) {
    int i = blockIdx.x * blockDim.x + threadIdx.x;
    if (i < NN * D1) g_h[i] = 0.f;
    if (i < NN * H1) g_den1[i] = 0.f;
    if (i < NN) g_den2[i] = 0.f;
    if (i < NN * D2) out[i] = 0.f;
}

// -------- GEMM1: xp1 = x @ W1  (1e5 x 512 x 32) --------
// block 256 threads = 8(tx) x 32(ty); tile M=256 rows, 32 cols, KB=16
__global__ __launch_bounds__(256) void gemm1_kernel(const float* __restrict__ x,
                                                    const float* __restrict__ W) {
    __shared__ float xs[256][17];   // padded stride: conflict-free column reads
    __shared__ float ws[16][32];
    int t = threadIdx.x;
    int tx = t & 7;        // col group: cols tx*4..tx*4+3
    int ty = t >> 3;       // row group: rows ty*8..ty*8+7
    int row0 = blockIdx.x * 256;

    float acc[8][4];
#pragma unroll
    for (int i = 0; i < 8; i++)
#pragma unroll
        for (int j = 0; j < 4; j++) acc[i][j] = 0.f;

    for (int k0 = 0; k0 < F_IN; k0 += 16) {
        // load x tile: 256 rows x 16 k (1024 float4 total, 4 per thread)
#pragma unroll
        for (int i = 0; i < 4; i++) {
            int idx = t + 256 * i;
            int r = idx >> 2;
            int c4 = idx & 3;
            float4 v = make_float4(0.f, 0.f, 0.f, 0.f);
            int gr = row0 + r;
            if (gr < NN) v = *(const float4*)(x + (size_t)gr * F_IN + k0 + c4 * 4);
            xs[r][c4 * 4 + 0] = v.x;
            xs[r][c4 * 4 + 1] = v.y;
            xs[r][c4 * 4 + 2] = v.z;
            xs[r][c4 * 4 + 3] = v.w;
        }
        // load W tile 16x32
#pragma unroll
        for (int i = 0; i < 2; i++) {
            int idx = t + 256 * i;
            int r = idx >> 5, c = idx & 31;
            ws[r][c] = W[(k0 + r) * 32 + c];
        }
        __syncthreads();
#pragma unroll
        for (int kk = 0; kk < 16; kk++) {
            float wv[4];
#pragma unroll
            for (int j = 0; j < 4; j++) wv[j] = ws[kk][tx * 4 + j];
#pragma unroll
            for (int i = 0; i < 8; i++) {
                float xv = xs[ty * 8 + i][kk];
#pragma unroll
                for (int j = 0; j < 4; j++) acc[i][j] += xv * wv[j];
            }
        }
        __syncthreads();
    }
#pragma unroll
    for (int i = 0; i < 8; i++) {
        int gr = row0 + ty * 8 + i;
        if (gr < NN) {
            float4 o = make_float4(acc[i][0], acc[i][1], acc[i][2], acc[i][3]);
            *(float4*)(g_xp1 + (size_t)gr * D1 + tx * 4) = o;
        }
    }
}

// -------- attention coefficients layer 1 --------
__global__ void att1_kernel(const float* __restrict__ att_src,
                            const float* __restrict__ att_dst) {
    int n = blockIdx.x * blockDim.x + threadIdx.x;
    if (n >= NN) return;
    float as[H1], ad[H1];
#pragma unroll
    for (int h = 0; h < H1; h++) { as[h] = 0.f; ad[h] = 0.f; }
#pragma unroll
    for (int h = 0; h < H1; h++) {
#pragma unroll
        for (int c = 0; c < C1; c++) {
            float v = g_xp1[n * D1 + h * C1 + c];
            as[h] += v * __ldg(att_src + h * C1 + c);
            ad[h] += v * __ldg(att_dst + h * C1 + c);
        }
    }
    *(float4*)(g_as1 + n * 4) = make_float4(as[0], as[1], as[2], as[3]);
    *(float4*)(g_ad1 + n * 4) = make_float4(ad[0], ad[1], ad[2], ad[3]);
}

// -------- layer-1 edge score + denom --------
__global__ void score1_kernel(const int* __restrict__ ei) {
    int e = blockIdx.x * blockDim.x + threadIdx.x;
    if (e >= EE + NN) return;
    int src, dst;
    if (e < EE) { src = ei[e]; dst = ei[EE + e]; }
    else { src = e - EE; dst = src; }
    float4 s4 = *(const float4*)(g_as1 + src * 4);
    float4 d4 = *(const float4*)(g_ad1 + dst * 4);
    float s0 = __expf(lrelu(s4.x + d4.x));
    float s1 = __expf(lrelu(s4.y + d4.y));
    float s2 = __expf(lrelu(s4.z + d4.z));
    float s3 = __expf(lrelu(s4.w + d4.w));
    red_add_v4(g_den1 + dst * 4, s0, s1, s2, s3);
}

// -------- layer-1 aggregation: 4 threads per edge (one per head) --------
__global__ void agg1_kernel(const int* __restrict__ ei) {
    int t = blockIdx.x * blockDim.x + threadIdx.x;
    if (t >= 4 * (EE + NN)) return;
    int e = t >> 2;
    int h = t & 3;
    int src, dst;
    if (e < EE) { src = ei[e]; dst = ei[EE + e]; }
    else { src = e - EE; dst = src; }
    float s = __expf(lrelu(g_as1[src * 4 + h] + g_ad1[dst * 4 + h]));
    float alpha = s / g_den1[dst * 4 + h];
    const float4* xr = (const float4*)(g_xp1 + src * D1 + h * C1);
    float4 a = xr[0], b = xr[1];
    float* o = g_h + dst * D1 + h * C1;
    red_add_v4(o, a.x * alpha, a.y * alpha, a.z * alpha, a.w * alpha);
    red_add_v4(o + 4, b.x * alpha, b.y * alpha, b.z * alpha, b.w * alpha);
}

// -------- node layer-1 epilogue fused with GEMM2 + att2 --------
__global__ __launch_bounds__(256) void node1_kernel(const float* __restrict__ b1,
                                                    const float* __restrict__ W2,
                                                    const float* __restrict__ as2w,
                                                    const float* __restrict__ ad2w) {
    __shared__ float w2s[D1 * D2];
    __shared__ float b1s[D1];
    __shared__ float a2s[D2], a2d[D2];
    int t = threadIdx.x;
    if (t < D1 * D2) w2s[t] = W2[t];
    if (t < D1) b1s[t] = b1[t];
    if (t < D2) { a2s[t] = as2w[t]; a2d[t] = ad2w[t]; }
    __syncthreads();
    int n = blockIdx.x * blockDim.x + t;
    if (n >= NN) return;
    float h[D1];
#pragma unroll
    for (int k = 0; k < D1; k++) {
        float v = g_h[n * D1 + k] + b1s[k];
        h[k] = v > 0.f ? v : expm1f(v);   // elu
    }
    float xp[D2];
#pragma unroll
    for (int c = 0; c < D2; c++) xp[c] = 0.f;
#pragma unroll
    for (int k = 0; k < D1; k++) {
#pragma unroll
        for (int c = 0; c < D2; c++) xp[c] += h[k] * w2s[k * D2 + c];
    }
    float as = 0.f, ad = 0.f;
#pragma unroll
    for (int c = 0; c < D2; c++) { as += xp[c] * a2s[c]; ad += xp[c] * a2d[c]; }
    *(float4*)(g_xp2 + n * D2) = make_float4(xp[0], xp[1], xp[2], xp[3]);
    *(float4*)(g_xp2 + n * D2 + 4) = make_float4(xp[4], xp[5], xp[6], xp[7]);
    g_as2[n] = as;
    g_ad2[n] = ad;
}

// -------- layer-2 edge score --------
__global__ void score2_kernel(const int* __restrict__ ei) {
    int e = blockIdx.x * blockDim.x + threadIdx.x;
    if (e >= EE + NN) return;
    int src, dst;
    if (e < EE) { src = ei[e]; dst = ei[EE + e]; }
    else { src = e - EE; dst = src; }
    float s = __expf(lrelu(g_as2[src] + g_ad2[dst]));
    atomicAdd(g_den2 + dst, s);
}

// -------- layer-2 aggregation: 2 threads per edge --------
__global__ void agg2_kernel(const int* __restrict__ ei, float* __restrict__ out) {
    int t = blockIdx.x * blockDim.x + threadIdx.x;
    if (t >= 2 * (EE + NN)) return;
    int e = t >> 1;
    int q = t & 1;
    int src, dst;
    if (e < EE) { src = ei[e]; dst = ei[EE + e]; }
    else { src = e - EE; dst = src; }
    float s = __expf(lrelu(g_as2[src] + g_ad2[dst]));
    float alpha = s / g_den2[dst];
    float4 v = ((const float4*)(g_xp2 + src * D2))[q];
    red_add_v4(out + dst * D2 + q * 4, v.x * alpha, v.y * alpha, v.z * alpha, v.w * alpha);
}

// -------- final bias --------
__global__ void bias2_kernel(float* __restrict__ out, const float* __restrict__ b2) {
    int i = blockIdx.x * blockDim.x + threadIdx.x;
    if (i < NN * D2) out[i] += b2[i & 7];
}

extern "C" void kernel_launch(void* const* d_in, const int* in_sizes, int n_in,
                              void* d_out, int out_size) {
    const float* x        = (const float*)d_in[0];
    const int*   ei       = (const int*)d_in[1];
    const float* W1       = (const float*)d_in[2];
    const float* att_src1 = (const float*)d_in[3];
    const float* att_dst1 = (const float*)d_in[4];
    const float* b1       = (const float*)d_in[5];
    const float* W2       = (const float*)d_in[6];
    const float* att_src2 = (const float*)d_in[7];
    const float* att_dst2 = (const float*)d_in[8];
    const float* b2       = (const float*)d_in[9];
    float* out = (float*)d_out;

    const int TB = 256;
    int nE = EE + NN;

    zero_kernel<<<(NN * D1 + TB - 1) / TB, TB>>>(out);
    gemm1_kernel<<<(NN + 255) / 256, 256>>>(x, W1);
    att1_kernel<<<(NN + TB - 1) / TB, TB>>>(att_src1, att_dst1);
    score1_kernel<<<(nE + TB - 1) / TB, TB>>>(ei);
    agg1_kernel<<<(4 * nE + TB - 1) / TB, TB>>>(ei);
    node1_kernel<<<(NN + TB - 1) / TB, TB>>>(b1, W2, att_src2, att_dst2);
    score2_kernel<<<(nE + TB - 1) / TB, TB>>>(ei);
    agg2_kernel<<<(2 * nE + TB - 1) / TB, TB>>>(ei, out);
    bias2_kernel<<<(NN * D2 + TB - 1) / TB, TB>>>(out, b2);
}

// round 2
// speedup vs baseline: 1.4536x; 1.4536x over previous
#include <cuda_runtime.h>
#include <cuda_bf16.h>

#define NN 100000
#define EE 3200000
#define F_IN 512
#define H1 4
#define C1 8
#define D1 32   // H1*C1
#define D2 8    // num classes
#define ETOT (EE + NN)

typedef unsigned long long ull;

// -------- scratch (device globals; no allocation allowed) --------
__device__ int   g_deg[NN];          // degree incl. self-loop
__device__ int   g_off[NN];          // exclusive segment offsets
__device__ int   g_bsum[128];        // scan block sums
__device__ int   g_cur[NN];          // scatter cursors
__device__ int   g_srcs[ETOT];       // dst-sorted source indices
__device__ float g_xp1[NN * D1];     // layer-1 transformed features
__device__ float g_as1[NN * H1];
__device__ float g_ad1[NN * H1];
__device__ float g_h[NN * D1];       // layer-1 aggregate (normalized)
__device__ float g_xp2[NN * D2];
__device__ float g_as2[NN];
__device__ float g_ad2[NN];

__device__ __forceinline__ float lrelu(float v) { return v > 0.f ? v : 0.2f * v; }

__device__ __forceinline__ ull fma2(ull a, ull b, ull c) {
    ull d;
    asm("fma.rn.f32x2 %0, %1, %2, %3;" : "=l"(d) : "l"(a), "l"(b), "l"(c));
    return d;
}
__device__ __forceinline__ ull pack2(float v) {
    ull r; unsigned u = __float_as_uint(v);
    asm("mov.b64 %0, {%1,%1};" : "=l"(r) : "r"(u));
    return r;
}
__device__ __forceinline__ void unpack2(ull v, float& lo, float& hi) {
    unsigned a, b;
    asm("mov.b64 {%0,%1}, %2;" : "=r"(a), "=r"(b) : "l"(v));
    lo = __uint_as_float(a); hi = __uint_as_float(b);
}

// ================= CSR build =================
__global__ void init_deg_kernel() {
    int i = blockIdx.x * blockDim.x + threadIdx.x;
    if (i < NN) g_deg[i] = 1;   // self-loop
}

__global__ void hist_kernel(const int* __restrict__ ei) {
    int e = blockIdx.x * blockDim.x + threadIdx.x;
    if (e < EE) atomicAdd(&g_deg[ei[EE + e]], 1);
}

// 98 blocks x 256 threads x 4 items = 100352 slots
__global__ __launch_bounds__(256) void scan_local_kernel() {
    __shared__ int ssum[256];
    int b = blockIdx.x, t = threadIdx.x;
    int base = b * 1024 + t * 4;
    int v[4];
#pragma unroll
    for (int j = 0; j < 4; j++) v[j] = (base + j < NN) ? g_deg[base + j] : 0;
    int run = 0;
#pragma unroll
    for (int j = 0; j < 4; j++) { int tmp = v[j]; v[j] = run; run += tmp; }
    ssum[t] = run;
    __syncthreads();
#pragma unroll
    for (int s = 1; s < 256; s <<= 1) {
        int x = (t >= s) ? ssum[t - s] : 0;
        __syncthreads();
        ssum[t] += x;
        __syncthreads();
    }
    int toff = (t > 0) ? ssum[t - 1] : 0;
#pragma unroll
    for (int j = 0; j < 4; j++)
        if (base + j < NN) g_off[base + j] = toff + v[j];
    if (t == 255) g_bsum[b] = ssum[255];
}

__global__ void scan_bsum_kernel() {
    __shared__ int s[128];
    int t = threadIdx.x;
    s[t] = (t < 98) ? g_bsum[t] : 0;
    __syncthreads();
#pragma unroll
    for (int st = 1; st < 128; st <<= 1) {
        int x = (t >= st) ? s[t - st] : 0;
        __syncthreads();
        s[t] += x;
        __syncthreads();
    }
    if (t < 98) g_bsum[t] = (t > 0) ? s[t - 1] : 0;
}

__global__ void scan_add_kernel() {
    int i = blockIdx.x * blockDim.x + threadIdx.x;
    if (i >= NN) return;
    int off = g_off[i] + g_bsum[i >> 10];
    g_off[i] = off;
    g_srcs[off] = i;       // self-loop placed first
    g_cur[i] = off + 1;
}

__global__ void scatter_kernel(const int* __restrict__ ei) {
    int e = blockIdx.x * blockDim.x + threadIdx.x;
    if (e >= EE) return;
    int dst = ei[EE + e];
    int src = ei[e];
    int pos = atomicAdd(&g_cur[dst], 1);
    g_srcs[pos] = src;
}

// ================= GEMM1 (f32x2) + fused att1 =================
// block 256 = 4(tx: 8 cols = one head) x 64(ty: 4 rows); tile M=256, K-step 16
__global__ __launch_bounds__(256) void gemm1_kernel(const float* __restrict__ x,
                                                    const float* __restrict__ W,
                                                    const float* __restrict__ att_src,
                                                    const float* __restrict__ att_dst) {
    __shared__ float xs[256][17];
    __shared__ float ws[16][32];
    __shared__ float s_as[32], s_ad[32];
    int t = threadIdx.x;
    int tx = t & 3;        // head / col group (8 cols)
    int ty = t >> 2;       // row group (4 rows)
    int row0 = blockIdx.x * 256;
    if (t < 32) { s_as[t] = att_src[t]; s_ad[t] = att_dst[t]; }

    ull acc2[4][4];
#pragma unroll
    for (int i = 0; i < 4; i++)
#pragma unroll
        for (int j = 0; j < 4; j++) acc2[i][j] = 0ull;

    for (int k0 = 0; k0 < F_IN; k0 += 16) {
#pragma unroll
        for (int i = 0; i < 4; i++) {
            int idx = t + 256 * i;
            int r = idx >> 2;
            int c4 = idx & 3;
            float4 v = make_float4(0.f, 0.f, 0.f, 0.f);
            int gr = row0 + r;
            if (gr < NN) v = *(const float4*)(x + (size_t)gr * F_IN + k0 + c4 * 4);
            xs[r][c4 * 4 + 0] = v.x;
            xs[r][c4 * 4 + 1] = v.y;
            xs[r][c4 * 4 + 2] = v.z;
            xs[r][c4 * 4 + 3] = v.w;
        }
#pragma unroll
        for (int i = 0; i < 2; i++) {
            int idx = t + 256 * i;
            int r = idx >> 5, c = idx & 31;
            ws[r][c] = W[(k0 + r) * 32 + c];
        }
        __syncthreads();
#pragma unroll
        for (int kk = 0; kk < 16; kk++) {
            const ull* wp = (const ull*)(&ws[kk][tx * 8]);
            ull w0 = wp[0], w1 = wp[1], w2 = wp[2], w3 = wp[3];
#pragma unroll
            for (int i = 0; i < 4; i++) {
                ull xv2 = pack2(xs[ty * 4 + i][kk]);
                acc2[i][0] = fma2(xv2, w0, acc2[i][0]);
                acc2[i][1] = fma2(xv2, w1, acc2[i][1]);
                acc2[i][2] = fma2(xv2, w2, acc2[i][2]);
                acc2[i][3] = fma2(xv2, w3, acc2[i][3]);
            }
        }
        __syncthreads();
    }
#pragma unroll
    for (int i = 0; i < 4; i++) {
        int gr = row0 + ty * 4 + i;
        if (gr >= NN) continue;
        float a[8];
#pragma unroll
        for (int j = 0; j < 4; j++) unpack2(acc2[i][j], a[2 * j], a[2 * j + 1]);
        float as = 0.f, ad = 0.f;
#pragma unroll
        for (int j = 0; j < 8; j++) {
            as += a[j] * s_as[tx * 8 + j];
            ad += a[j] * s_ad[tx * 8 + j];
        }
        float* op = g_xp1 + (size_t)gr * D1 + tx * 8;
        *(float4*)(op)     = make_float4(a[0], a[1], a[2], a[3]);
        *(float4*)(op + 4) = make_float4(a[4], a[5], a[6], a[7]);
        g_as1[gr * 4 + tx] = as;
        g_ad1[gr * 4 + tx] = ad;
    }
}

// ================= layer-1 aggregation: warp per dst, 4 lanes/edge =================
__global__ __launch_bounds__(256) void agg1_kernel() {
    int w = (blockIdx.x * blockDim.x + threadIdx.x) >> 5;
    if (w >= NN) return;
    int lane = threadIdx.x & 31;
    int g = lane >> 2;     // edge slot 0..7
    int h = lane & 3;      // head
    int beg = g_off[w];
    int end = (w + 1 < NN) ? g_off[w + 1] : ETOT;
    float ad = g_ad1[w * 4 + h];
    float a0 = 0.f, a1 = 0.f, a2 = 0.f, a3 = 0.f;
    float a4 = 0.f, a5 = 0.f, a6 = 0.f, a7 = 0.f;
    float den = 0.f;
    for (int i = beg + g; i < end; i += 8) {
        int src = g_srcs[i];
        float as = g_as1[src * 4 + h];
        float s = __expf(lrelu(as + ad));
        den += s;
        const float4* p = (const float4*)(g_xp1 + (size_t)src * D1 + h * C1);
        float4 u = p[0], v = p[1];
        a0 += s * u.x; a1 += s * u.y; a2 += s * u.z; a3 += s * u.w;
        a4 += s * v.x; a5 += s * v.y; a6 += s * v.z; a7 += s * v.w;
    }
#pragma unroll
    for (int m = 4; m < 32; m <<= 1) {
        den += __shfl_xor_sync(0xffffffffu, den, m);
        a0 += __shfl_xor_sync(0xffffffffu, a0, m);
        a1 += __shfl_xor_sync(0xffffffffu, a1, m);
        a2 += __shfl_xor_sync(0xffffffffu, a2, m);
        a3 += __shfl_xor_sync(0xffffffffu, a3, m);
        a4 += __shfl_xor_sync(0xffffffffu, a4, m);
        a5 += __shfl_xor_sync(0xffffffffu, a5, m);
        a6 += __shfl_xor_sync(0xffffffffu, a6, m);
        a7 += __shfl_xor_sync(0xffffffffu, a7, m);
    }
    if (g == 0) {
        float inv = 1.f / den;
        float* o = g_h + (size_t)w * D1 + h * C1;
        *(float4*)(o)     = make_float4(a0 * inv, a1 * inv, a2 * inv, a3 * inv);
        *(float4*)(o + 4) = make_float4(a4 * inv, a5 * inv, a6 * inv, a7 * inv);
    }
}

// ================= node epilogue: bias + elu + GEMM2 + att2 =================
__global__ __launch_bounds__(256) void node1_kernel(const float* __restrict__ b1,
                                                    const float* __restrict__ W2,
                                                    const float* __restrict__ as2w,
                                                    const float* __restrict__ ad2w) {
    __shared__ float w2s[D1 * D2];
    __shared__ float b1s[D1];
    __shared__ float a2s[D2], a2d[D2];
    int t = threadIdx.x;
    if (t < D1 * D2) w2s[t] = W2[t];
    if (t < D1) b1s[t] = b1[t];
    if (t < D2) { a2s[t] = as2w[t]; a2d[t] = ad2w[t]; }
    __syncthreads();
    int n = blockIdx.x * blockDim.x + t;
    if (n >= NN) return;
    float h[D1];
#pragma unroll
    for (int k = 0; k < D1; k++) {
        float v = g_h[(size_t)n * D1 + k] + b1s[k];
        h[k] = v > 0.f ? v : expm1f(v);   // elu
    }
    float xp[D2];
#pragma unroll
    for (int c = 0; c < D2; c++) xp[c] = 0.f;
#pragma unroll
    for (int k = 0; k < D1; k++)
#pragma unroll
        for (int c = 0; c < D2; c++) xp[c] += h[k] * w2s[k * D2 + c];
    float as = 0.f, ad = 0.f;
#pragma unroll
    for (int c = 0; c < D2; c++) { as += xp[c] * a2s[c]; ad += xp[c] * a2d[c]; }
    *(float4*)(g_xp2 + (size_t)n * D2)     = make_float4(xp[0], xp[1], xp[2], xp[3]);
    *(float4*)(g_xp2 + (size_t)n * D2 + 4) = make_float4(xp[4], xp[5], xp[6], xp[7]);
    g_as2[n] = as;
    g_ad2[n] = ad;
}

// ================= layer-2 aggregation: warp per dst, lane per edge =================
__global__ __launch_bounds__(256) void agg2_kernel(float* __restrict__ out,
                                                   const float* __restrict__ b2) {
    int w = (blockIdx.x * blockDim.x + threadIdx.x) >> 5;
    if (w >= NN) return;
    int lane = threadIdx.x & 31;
    int beg = g_off[w];
    int end = (w + 1 < NN) ? g_off[w + 1] : ETOT;
    float ad = g_ad2[w];
    float a0 = 0.f, a1 = 0.f, a2 = 0.f, a3 = 0.f;
    float a4 = 0.f, a5 = 0.f, a6 = 0.f, a7 = 0.f;
    float den = 0.f;
    for (int i = beg + lane; i < end; i += 32) {
        int src = g_srcs[i];
        float s = __expf(lrelu(g_as2[src] + ad));
        den += s;
        const float4* p = (const float4*)(g_xp2 + (size_t)src * D2);
        float4 u = p[0], v = p[1];
        a0 += s * u.x; a1 += s * u.y; a2 += s * u.z; a3 += s * u.w;
        a4 += s * v.x; a5 += s * v.y; a6 += s * v.z; a7 += s * v.w;
    }
#pragma unroll
    for (int m = 1; m < 32; m <<= 1) {
        den += __shfl_xor_sync(0xffffffffu, den, m);
        a0 += __shfl_xor_sync(0xffffffffu, a0, m);
        a1 += __shfl_xor_sync(0xffffffffu, a1, m);
        a2 += __shfl_xor_sync(0xffffffffu, a2, m);
        a3 += __shfl_xor_sync(0xffffffffu, a3, m);
        a4 += __shfl_xor_sync(0xffffffffu, a4, m);
        a5 += __shfl_xor_sync(0xffffffffu, a5, m);
        a6 += __shfl_xor_sync(0xffffffffu, a6, m);
        a7 += __shfl_xor_sync(0xffffffffu, a7, m);
    }
    if (lane == 0) {
        float inv = 1.f / den;
        float* o = out + (size_t)w * D2;
        *(float4*)(o)     = make_float4(a0 * inv + b2[0], a1 * inv + b2[1],
                                        a2 * inv + b2[2], a3 * inv + b2[3]);
        *(float4*)(o + 4) = make_float4(a4 * inv + b2[4], a5 * inv + b2[5],
                                        a6 * inv + b2[6], a7 * inv + b2[7]);
    }
}

extern "C" void kernel_launch(void* const* d_in, const int* in_sizes, int n_in,
                              void* d_out, int out_size) {
    const float* x        = (const float*)d_in[0];
    const int*   ei       = (const int*)d_in[1];
    const float* W1       = (const float*)d_in[2];
    const float* att_src1 = (const float*)d_in[3];
    const float* att_dst1 = (const float*)d_in[4];
    const float* b1       = (const float*)d_in[5];
    const float* W2       = (const float*)d_in[6];
    const float* att_src2 = (const float*)d_in[7];
    const float* att_dst2 = (const float*)d_in[8];
    const float* b2       = (const float*)d_in[9];
    float* out = (float*)d_out;

    const int TB = 256;
    int gN = (NN + TB - 1) / TB;           // 391
    int gE = (EE + TB - 1) / TB;           // 12500
    int gW = (NN * 32 + TB - 1) / TB;      // 12500 (warp per node)

    init_deg_kernel<<<gN, TB>>>();
    hist_kernel<<<gE, TB>>>(ei);
    scan_local_kernel<<<98, 256>>>();
    scan_bsum_kernel<<<1, 128>>>();
    scan_add_kernel<<<gN, TB>>>();
    scatter_kernel<<<gE, TB>>>(ei);
    gemm1_kernel<<<gN, 256>>>(x, W1, att_src1, att_dst1);
    agg1_kernel<<<gW, TB>>>();
    node1_kernel<<<gN, TB>>>(b1, W2, att_src2, att_dst2);
    agg2_kernel<<<gW, TB>>>(out, b2);
}